// round 1
// baseline (speedup 1.0000x reference)
#include <cuda_runtime.h>

typedef unsigned long long ull;

#define S_LEN   1024
#define D_DIM   64
#define NPOS    64
#define KT      64
#define NTILES  (S_LEN / KT)
#define WARPS   4
#define CTA_ROWS (WARPS * 32)
#define SCALE_F 0.125f

// shared memory layout (in floats)
#define PE_STRIDE 68
#define PE_FLOATS (NPOS * PE_STRIDE)            // 4352 (also reused as k-tile: KT*D=4096)
#define LG_STRIDE 66
#define LG_FLOATS (CTA_ROWS * LG_STRIDE)        // 8448
#define ST_STRIDE 66
#define ST_WARP_FLOATS (32 * ST_STRIDE)         // 2112
#define ST_FLOATS (WARPS * ST_WARP_FLOATS)      // 8448
#define SMEM_BYTES ((PE_FLOATS + LG_FLOATS + ST_FLOATS) * 4)   // 84992 B

__device__ __forceinline__ ull fma2(ull a, ull b, ull c) {
    ull d;
    asm("fma.rn.f32x2 %0, %1, %2, %3;" : "=l"(d) : "l"(a), "l"(b), "l"(c));
    return d;
}
__device__ __forceinline__ float hsum2(ull a) {
    unsigned lo, hi;
    asm("mov.b64 {%0, %1}, %2;" : "=r"(lo), "=r"(hi) : "l"(a));
    return __uint_as_float(lo) + __uint_as_float(hi);
}

__global__ void __launch_bounds__(WARPS * 32)
cope_kernel(const float* __restrict__ q, const float* __restrict__ kmat,
            const float* __restrict__ pos_emb, const int* __restrict__ flag_p,
            float* __restrict__ out)
{
    extern __shared__ float smem[];
    float* pe_t  = smem;                  // pos_emb transposed; later aliased as k tile
    float* lgt   = smem + PE_FLOATS;      // per-row logits_int [CTA_ROWS][66]
    float* stg   = lgt + LG_FLOATS;       // per-warp output staging [32][66]

    const int tid  = threadIdx.x;
    const int wid  = tid >> 5;
    const int lane = tid & 31;
    const long long grow = (long long)blockIdx.x * CTA_ROWS + tid;  // global row index in [0, B*S)
    const int b = (int)(grow >> 10);                                 // S = 1024
    float* mylg  = lgt + tid * LG_STRIDE;
    float* mystg = stg + wid * ST_WARP_FLOATS;

    // ---- Phase 0: pos_emb -> smem, transposed: pe_t[n][d] = pos_emb[d*NPOS + n]
    for (int i = tid; i < D_DIM * NPOS; i += WARPS * 32) {
        int d = i >> 6, n = i & 63;
        pe_t[n * PE_STRIDE + d] = pos_emb[i];
    }
    mylg[NPOS] = 0.0f;   // guard so the ceil gather at pos==63 reads a finite value
    __syncthreads();

    // ---- Phase 1: logits_int[row][n] = sum_d base[row][d] * pos_emb[d][n]
    const int flag = *flag_p;
    ull qp[32];
    {
        const ulonglong2* bp = (const ulonglong2*)((flag ? q : kmat) + grow * D_DIM);
        #pragma unroll
        for (int j = 0; j < 16; ++j) { ulonglong2 v = bp[j]; qp[2*j] = v.x; qp[2*j+1] = v.y; }
    }
    for (int n = 0; n < NPOS; ++n) {
        const ulonglong2* pr = (const ulonglong2*)(pe_t + n * PE_STRIDE);
        ull acc = 0ull;
        #pragma unroll
        for (int j = 0; j < 16; ++j) {
            ulonglong2 v = pr[j];
            acc = fma2(qp[2*j],     v.x, acc);
            acc = fma2(qp[2*j + 1], v.y, acc);
        }
        mylg[n] = hsum2(acc);
    }
    const float l63 = mylg[NPOS - 1];

    // ---- reload q row packed (gates always use q; base may have been k)
    {
        const ulonglong2* bp = (const ulonglong2*)(q + grow * D_DIM);
        #pragma unroll
        for (int j = 0; j < 16; ++j) { ulonglong2 v = bp[j]; qp[2*j] = v.x; qp[2*j+1] = v.y; }
    }

    // ---- Phase 2: reverse sweep over key tiles with saturation early-exit
    float carry = 0.0f;
    int t = NTILES - 1;
    for (; t >= 0; --t) {
        if (__syncthreads_and(carry >= 63.0f)) break;   // whole CTA saturated -> bulk fill below
        // cooperative k-tile load (overwrites pe_t region; barrier above orders it)
        {
            const float4* src = (const float4*)(kmat + ((long long)b * S_LEN + t * KT) * D_DIM);
            float4* dst = (float4*)pe_t;
            #pragma unroll
            for (int i = tid; i < KT * D_DIM / 4; i += WARPS * 32) dst[i] = src[i];
        }
        __syncthreads();
        const int kb = t * KT;

        if (__all_sync(0xffffffffu, carry >= 63.0f)) {
            // warp fully saturated: this tile is a per-row constant fill
            for (int r = 0; r < 32; ++r) {
                float v = __shfl_sync(0xffffffffu, l63, r);
                long long orow = (long long)blockIdx.x * CTA_ROWS + wid * 32 + r;
                float2* dst = (float2*)(out + orow * S_LEN + kb);
                dst[lane] = make_float2(v, v);
            }
        } else {
            // descending key order, groups of 8 for ILP; carry prefix is the only serial part
            for (int kk0 = KT - 8; kk0 >= 0; kk0 -= 8) {
                ull acc[8];
                #pragma unroll
                for (int j = 0; j < 8; ++j) acc[j] = 0ull;
                #pragma unroll
                for (int i = 0; i < 16; ++i) {
                    #pragma unroll
                    for (int j = 0; j < 8; ++j) {
                        ulonglong2 v = *(const ulonglong2*)(pe_t + (kk0 + j) * D_DIM + i * 4);
                        acc[j] = fma2(qp[2*i],     v.x, acc[j]);
                        acc[j] = fma2(qp[2*i + 1], v.y, acc[j]);
                    }
                }
                float g[8];
                #pragma unroll
                for (int j = 0; j < 8; ++j) {
                    float x = hsum2(acc[j]) * SCALE_F;
                    g[j] = __fdividef(1.0f, 1.0f + __expf(-x));
                }
                #pragma unroll
                for (int j = 7; j >= 0; --j) {
                    carry += g[j];
                    float pos = fminf(carry, 63.0f);
                    float pf  = floorf(pos);
                    int   ip  = (int)pf;
                    float w   = pos - pf;
                    float lf  = mylg[ip];
                    float lc  = mylg[ip + 1];
                    mystg[lane * ST_STRIDE + kk0 + j] = lc * w + lf * (1.0f - w);
                }
            }
            __syncwarp();
            // coalesced transpose write-out of the staged tile
            for (int r = 0; r < 32; ++r) {
                long long orow = (long long)blockIdx.x * CTA_ROWS + wid * 32 + r;
                float2 v = *(const float2*)(mystg + r * ST_STRIDE + 2 * lane);
                *(float2*)(out + orow * S_LEN + kb + 2 * lane) = v;
            }
            __syncwarp();
        }
    }

    // ---- Phase 3: bulk constant fill for all remaining (fully saturated) keys
    const int kend = (t + 1) * KT;
    if (kend > 0) {
        for (int r = 0; r < 32; ++r) {
            float v = __shfl_sync(0xffffffffu, l63, r);
            float4 vv = make_float4(v, v, v, v);
            long long orow = (long long)blockIdx.x * CTA_ROWS + wid * 32 + r;
            float* dst = out + orow * S_LEN;
            for (int c = 4 * lane; c < kend; c += 128)
                *(float4*)(dst + c) = vv;
        }
    }
}

extern "C" void kernel_launch(void* const* d_in, const int* in_sizes, int n_in,
                              void* d_out, int out_size) {
    const float* q    = (const float*)d_in[0];
    const float* k    = (const float*)d_in[1];
    // d_in[2] = v (unused in mode 0)
    const float* pe   = (const float*)d_in[3];
    // d_in[4] = w_k (unused)
    const int*   flag = (const int*)d_in[5];
    float* out = (float*)d_out;

    cudaFuncSetAttribute(cope_kernel, cudaFuncAttributeMaxDynamicSharedMemorySize, SMEM_BYTES);
    const int grid = (32 * S_LEN) / CTA_ROWS;   // 256 CTAs, all resident in one wave
    cope_kernel<<<grid, WARPS * 32, SMEM_BYTES>>>(q, k, pe, flag, out);
}